// round 17
// baseline (speedup 1.0000x reference)
#include <cuda_runtime.h>
#include <math_constants.h>
#include <cstdint>

// ============================================================================
// Exact k-NN: packed-pair IMAD.WIDE coarse scan (2 MACs per fma-pipe op)
// + exact fp32 rescore.
//   Pack 2 dims (7-bit biased, scale 12) per u32 at 2^21 spacing; base pairs
//   swapped within word => mad.wide.u32 accumulates q0b0+q1b1 in bits 21..41.
//   Per row: 64 IMAD.WIDE instead of 128 FFMA  -> fma-pipe demand halved.
//   1) quant:  packed words + exact fp32 |b|^2 + key-base B[r]=bsq+(8/9)Sb''
//   2) coarse: thread-per-query scan, 4 u64 acc chains, top-16/chunk on
//              key = B[r] - (2/144)*S_mid   (per-query terms rank-invariant)
//   3) merge:  37 chunk lists -> global top-32   4) rescore: exact fp32
// ============================================================================

#define D128  128
#define NC    37
#define TB    64         // rows per tile; 64 x 256B = 16 KB per buffer
#define KCC   16
#define KG    32
#define MAXN  262144
#define MAXQ  1024
#define QSC   12.0f                  // quant scale
#define KS    (-2.0f / 144.0f)       // key scale = -2/QSC^2

typedef unsigned long long ull;

__device__ __align__(256) uint32_t g_b8[MAXN * 64];   // packed base (swapped pairs)
__device__ __align__(256) uint32_t g_q8[MAXQ * 64];   // packed query
__device__ float g_bsq [MAXN];   // exact |b|^2 (for rescore)
__device__ float g_bkey[MAXN];   // B[r] = bsq + (8/9)*Sb''
__device__ float g_qd1 [MAXQ];   // dummies for query prepass
__device__ float g_qd2 [MAXQ];
__device__ float g_ckey[NC * KCC * MAXQ];
__device__ int   g_cidx[NC * KCC * MAXQ];
__device__ int   g_sel [MAXQ * KG];

__device__ __forceinline__ void madw(ull& acc, uint32_t a, uint32_t b) {
    asm("mad.wide.u32 %0, %1, %2, %0;" : "+l"(acc) : "r"(a), "r"(b));
}

template<int K> __device__ __forceinline__
void topk_insert(float (&td)[K], int (&ti)[K], float& kmax, float v, int idx) {
    bool done = false;
    #pragma unroll
    for (int s = 0; s < K; ++s)
        if (!done && td[s] == kmax) { td[s] = v; ti[s] = idx; done = true; }
    float m = td[0];
    #pragma unroll
    for (int s = 1; s < K; ++s) m = fmaxf(m, td[s]);
    kmax = m;
}

// ---------------------------------------------------------------------------
// Quantize + pack (pairs; base swapped) + exact |row|^2 + key-base.
// One warp per row; lane owns dims 4l..4l+3 -> packed words 2l, 2l+1.
// ---------------------------------------------------------------------------
__global__ void quant_kernel(const float* __restrict__ src,
                             uint32_t* __restrict__ dst,
                             float* __restrict__ bsq_out,
                             float* __restrict__ key_out,
                             int N, int swap) {
    int row = blockIdx.x * 8 + (threadIdx.x >> 5);
    if (row >= N) return;
    int lane = threadIdx.x & 31;
    float4 v = reinterpret_cast<const float4*>(src)[(size_t)row * 32 + lane];

    int q0 = min(max(__float2int_rn(v.x * QSC) + 64, 0), 127);
    int q1 = min(max(__float2int_rn(v.y * QSC) + 64, 0), 127);
    int q2 = min(max(__float2int_rn(v.z * QSC) + 64, 0), 127);
    int q3 = min(max(__float2int_rn(v.w * QSC) + 64, 0), 127);

    uint32_t w0 = swap ? ((uint32_t)q1 | ((uint32_t)q0 << 21))
                       : ((uint32_t)q0 | ((uint32_t)q1 << 21));
    uint32_t w1 = swap ? ((uint32_t)q3 | ((uint32_t)q2 << 21))
                       : ((uint32_t)q2 | ((uint32_t)q3 << 21));
    reinterpret_cast<uint2*>(dst)[(size_t)row * 32 + lane] = make_uint2(w0, w1);

    float s  = v.x * v.x + v.y * v.y + v.z * v.z + v.w * v.w;
    int   si = (q0 + q1 + q2 + q3) - 256;     // sum of biased-removed values
    #pragma unroll
    for (int off = 16; off > 0; off >>= 1) {
        s  += __shfl_xor_sync(0xFFFFFFFFu, s, off);
        si += __shfl_xor_sync(0xFFFFFFFFu, si, off);
    }
    if (lane == 0) {
        bsq_out[row] = s;
        key_out[row] = fmaf(8.0f / 9.0f, (float)si, s);   // bsq + (2*64/144)*Sb''
    }
}

// ---------------------------------------------------------------------------
// Coarse scan: grid (NC, Q/256), block 256, 1 thread = 1 query.
// Query: 64 packed words in registers. 64-row packed tiles in smem
// (broadcast LDS.128), reg-prefetch double buffer, 1 barrier/tile.
// Per row: 16 LDS.128 + 64 IMAD.WIDE (4 chains) + extract + key.
// ---------------------------------------------------------------------------
__global__ void __launch_bounds__(256)
knn_coarse_mw(const uint32_t* __restrict__ b8,
              const uint32_t* __restrict__ q8,
              int N, int Q) {
    __shared__ __align__(16) uint32_t sB[2][TB * 64];   // 2 x 16 KB
    __shared__ float sKB[2][TB];

    const int tid   = threadIdx.x;
    const int chunk = blockIdx.x;
    const int qt    = blockIdx.y;

    const int chunk_len = (N + NC - 1) / NC;
    const int cs = chunk * chunk_len;
    const int ce = min(cs + chunk_len, N);
    const int ntiles = (ce - cs + TB - 1) / TB;

    const uint4* b16 = reinterpret_cast<const uint4*>(b8);   // 16 uint4 / row

    // query packed words -> 64 registers
    uint32_t qw[64];
    {
        int q = min(qt * 256 + tid, Q - 1);
        const uint32_t* qrow = q8 + (size_t)q * 64;
        #pragma unroll
        for (int i = 0; i < 64; ++i) qw[i] = qrow[i];
    }

    float td[KCC]; int ti[KCC];
    #pragma unroll
    for (int j = 0; j < KCC; ++j) { td[j] = CUDART_INF_F; ti[j] = -1; }
    float kmax = CUDART_INF_F;

    // prologue: tile 0 -> buffer 0 (tile = 64 rows x 16 uint4 = 1024 uint4)
    {
        #pragma unroll
        for (int j = 0; j < 4; ++j) {
            int c = tid + j * 256;
            int row = c >> 4, ch = c & 15;
            int gr = min(cs + row, N - 1);
            reinterpret_cast<uint4*>(&sB[0][0])[c] = b16[(size_t)gr * 16 + ch];
        }
        if (tid < TB) {
            int gr = cs + tid;
            sKB[0][tid] = (gr < ce) ? g_bkey[gr] : CUDART_INF_F;
        }
        __syncthreads();
    }

    for (int t = 0; t < ntiles; ++t) {
        const int s = t & 1;
        const int n0 = cs + t * TB;
        const bool pf = (t + 1 < ntiles);

        // prefetch t+1 into registers (lands during IMAD phase)
        uint4 r0, r1, r2, r3; float rb = CUDART_INF_F;
        if (pf) {
            const int n0n = n0 + TB;
            { int c = tid;       int row = c >> 4, ch = c & 15;
              r0 = b16[(size_t)min(n0n + row, N - 1) * 16 + ch]; }
            { int c = tid + 256; int row = c >> 4, ch = c & 15;
              r1 = b16[(size_t)min(n0n + row, N - 1) * 16 + ch]; }
            { int c = tid + 512; int row = c >> 4, ch = c & 15;
              r2 = b16[(size_t)min(n0n + row, N - 1) * 16 + ch]; }
            { int c = tid + 768; int row = c >> 4, ch = c & 15;
              r3 = b16[(size_t)min(n0n + row, N - 1) * 16 + ch]; }
            if (tid < TB) {
                int gr = n0n + tid;
                rb = (gr < ce) ? g_bkey[gr] : CUDART_INF_F;
            }
        }

        // scan 64 rows: 16 LDS.128 + 64 mad.wide (4 u64 chains) per row.
        // OOB rows carry sKB = +INF -> key never inserted.
        #pragma unroll 1
        for (int r = 0; r < TB; ++r) {
            const uint4* bp = reinterpret_cast<const uint4*>(&sB[s][r * 64]);
            ull a0 = 0ull, a1 = 0ull, a2 = 0ull, a3 = 0ull;
            #pragma unroll
            for (int i = 0; i < 16; ++i) {
                uint4 w = bp[i];
                madw(a0, qw[4 * i + 0], w.x);
                madw(a1, qw[4 * i + 1], w.y);
                madw(a2, qw[4 * i + 2], w.z);
                madw(a3, qw[4 * i + 3], w.w);
            }
            ull V = (a0 + a1) + (a2 + a3);
            uint32_t smid = (uint32_t)(V >> 21) & 0x1FFFFFu;
            float key = fmaf(KS, (float)smid, sKB[s][r]);
            if (key < kmax) topk_insert(td, ti, kmax, key, n0 + r);
        }

        // store prefetched tile into other buffer, single barrier
        if (pf) {
            const int s1 = s ^ 1;
            reinterpret_cast<uint4*>(&sB[s1][0])[tid]       = r0;
            reinterpret_cast<uint4*>(&sB[s1][0])[tid + 256] = r1;
            reinterpret_cast<uint4*>(&sB[s1][0])[tid + 512] = r2;
            reinterpret_cast<uint4*>(&sB[s1][0])[tid + 768] = r3;
            if (tid < TB) sKB[s1][tid] = rb;
        }
        __syncthreads();
    }

    // write candidates (transposed layout for coalesced merge reads)
    int q = qt * 256 + tid;
    if (q < Q) {
        #pragma unroll
        for (int j = 0; j < KCC; ++j) {
            g_ckey[(chunk * KCC + j) * MAXQ + q] = td[j];
            g_cidx[(chunk * KCC + j) * MAXQ + q] = ti[j];
        }
    }
}

// ---------------------------------------------------------------------------
// Merge NC*KCC chunk candidates -> global top-32 per query
// ---------------------------------------------------------------------------
__global__ void merge_kernel(int Q) {
    int q = blockIdx.x * blockDim.x + threadIdx.x;
    if (q >= Q) return;
    float td[KG]; int ti[KG];
    #pragma unroll
    for (int j = 0; j < KG; ++j) { td[j] = CUDART_INF_F; ti[j] = -1; }
    float kmax = CUDART_INF_F;
    for (int j = 0; j < NC * KCC; ++j) {
        float v = g_ckey[j * MAXQ + q];
        if (v < kmax) topk_insert(td, ti, kmax, v, g_cidx[j * MAXQ + q]);
    }
    #pragma unroll
    for (int j = 0; j < KG; ++j) g_sel[q * KG + j] = ti[j];
}

// ---------------------------------------------------------------------------
// Exact fp32 rescore of 32 candidates/query + final sort + output.
// 1 warp per query, lane = candidate.
// ---------------------------------------------------------------------------
__global__ void rescore_kernel(const float* __restrict__ base,
                               const float* __restrict__ query,
                               float* __restrict__ out, int N, int Q, int K) {
    __shared__ float sD[4][KG];
    __shared__ int   sI[4][KG];
    int w = threadIdx.x >> 5;
    int lane = threadIdx.x & 31;
    int q = blockIdx.x * 4 + w;
    if (q >= Q) return;

    int cand = g_sel[q * KG + lane];
    float d2;
    if (cand >= 0) {
        const float4* qrow = reinterpret_cast<const float4*>(query) + (size_t)q * 32;
        const float4* brow = reinterpret_cast<const float4*>(base) + (size_t)cand * 32;
        float dot = 0.f, qsq = 0.f;
        #pragma unroll
        for (int j = 0; j < 32; ++j) {
            float4 a = qrow[j], b = brow[j];
            dot += a.x * b.x + a.y * b.y + a.z * b.z + a.w * b.w;
            qsq += a.x * a.x + a.y * a.y + a.z * a.z + a.w * a.w;
        }
        d2 = qsq - 2.0f * dot + g_bsq[cand];
    } else {
        d2 = CUDART_INF_F; cand = 0x7fffffff;
    }
    sD[w][lane] = d2; sI[w][lane] = cand;
    __syncwarp();

    if (lane == 0) {
        float a[KG]; int b[KG];
        #pragma unroll
        for (int j = 0; j < KG; ++j) { a[j] = sD[w][j]; b[j] = sI[w][j]; }
        for (int r = 0; r < K; ++r) {
            int best = r;
            for (int j = r + 1; j < KG; ++j)
                if (a[j] < a[best] || (a[j] == a[best] && b[j] < b[best])) best = j;
            float tv = a[r]; a[r] = a[best]; a[best] = tv;
            int   ts = b[r]; b[r] = b[best]; b[best] = ts;
            out[(size_t)q * K + r]                 = (float)b[r];
            out[(size_t)Q * K + (size_t)q * K + r] = sqrtf(fmaxf(a[r], 0.0f));
        }
    }
}

// ---------------------------------------------------------------------------
extern "C" void kernel_launch(void* const* d_in, const int* in_sizes, int n_in,
                              void* d_out, int out_size) {
    const float* base  = (const float*)d_in[0];
    const float* query = (const float*)d_in[1];

    int N = in_sizes[0] / D128;
    int Q = in_sizes[1] / D128;
    int K = (Q > 0) ? out_size / (2 * Q) : 10;
    if (K <= 0 || K > KG) K = 10;

    uint32_t* b8;  cudaGetSymbolAddress((void**)&b8, g_b8);
    uint32_t* q8;  cudaGetSymbolAddress((void**)&q8, g_q8);
    float* bsq;    cudaGetSymbolAddress((void**)&bsq, g_bsq);
    float* bkey;   cudaGetSymbolAddress((void**)&bkey, g_bkey);
    float* qd1;    cudaGetSymbolAddress((void**)&qd1, g_qd1);
    float* qd2;    cudaGetSymbolAddress((void**)&qd2, g_qd2);

    quant_kernel<<<(N + 7) / 8, 256>>>(base, b8, bsq, bkey, N, 1);   // swapped
    quant_kernel<<<(Q + 7) / 8, 256>>>(query, q8, qd1, qd2, Q, 0);   // normal

    dim3 grid(NC, (Q + 255) / 256);
    knn_coarse_mw<<<grid, 256>>>(b8, q8, N, Q);

    merge_kernel<<<(Q + 255) / 256, 256>>>(Q);
    rescore_kernel<<<(Q + 3) / 4, 128>>>(base, query, (float*)d_out, N, Q, K);
}